// round 5
// baseline (speedup 1.0000x reference)
#include <cuda_runtime.h>
#include <cuda_fp16.h>
#include <cuda_bf16.h>
#include <mma.h>
#include <cstdint>

using namespace nvcuda;

#define N_NODES_MAX 50000
#define N_EDGES_MAX 800000
#define IN_F  256
#define OUT_F 128

// -------- device scratch --------
__device__ __align__(16) __half g_mh[N_NODES_MAX * OUT_F];  // relu(mean)*exp(-var)
__device__ __align__(16) __half g_vh[N_NODES_MAX * OUT_F];  // relu(var)*exp(-2var)
__device__ float g_norm1[N_NODES_MAX];
__device__ int   g_cnt[N_NODES_MAX];
__device__ int   g_rp[N_NODES_MAX + 1];
__device__ int   g_cur[N_NODES_MAX];
__device__ int   g_csrc[N_EDGES_MAX];

// ---------------------------------------------------------------------
__global__ void count_kernel(const int* __restrict__ edge_dst, int n_edges) {
    int e = blockIdx.x * blockDim.x + threadIdx.x;
    if (e < n_edges) atomicAdd(&g_cnt[edge_dst[e]], 1);
}

// Single-block fused scan: cnt -> rp (exclusive+1), cur, norm1. 1024 threads.
__global__ __launch_bounds__(1024)
void scan_fused_kernel(int n) {
    __shared__ int sh[1024];
    const int tid = threadIdx.x;
    const int per = (n + 1023) >> 10;
    const int start = tid * per;
    const int end = min(start + per, n);

    // pass 1: per-thread sum
    int s = 0;
    for (int i = start; i < end; i++) s += g_cnt[i];

    // block-wide Hillis-Steele scan (inclusive)
    sh[tid] = s;
    __syncthreads();
    for (int off = 1; off < 1024; off <<= 1) {
        int t = (tid >= off) ? sh[tid - off] : 0;
        __syncthreads();
        sh[tid] += t;
        __syncthreads();
    }
    int run = sh[tid] - s;   // exclusive prefix for this thread's range

    // pass 2: emit rp (inclusive at i -> rp[i+1]), cur (exclusive), norm1
    for (int i = start; i < end; i++) {
        int c = g_cnt[i];
        g_cur[i] = run;
        run += c;
        g_rp[i + 1] = run;
        g_norm1[i] = rsqrtf(fmaxf((float)c, 1.0f));
    }
    if (tid == 0) g_rp[0] = 0;
}

__global__ void fill_kernel(const int* __restrict__ edge_src,
                            const int* __restrict__ edge_dst, int n_edges) {
    int e = blockIdx.x * blockDim.x + threadIdx.x;
    if (e < n_edges) {
        int d = edge_dst[e];
        int pos = atomicAdd(&g_cur[d], 1);
        g_csrc[pos] = edge_src[e];
    }
}

// ---------------------------------------------------------------------
// Tensor-core dual GEMM, double-buffered smem + register prefetch pipeline.
// Block = 256 threads (8 warps), tile 128 rows x 128 cols x both matrices.
#define GBM 128
#define GKC 32
#define AS_LD 40            // 32 + 8 pad halves
#define WS_LD 136           // 128 + 8 pad halves
#define AS_BUF (GBM * AS_LD)          // halves per buffer: 5120
#define WS_BUF (GKC * WS_LD)          // halves per buffer: 4352
#define SM_AS_OFF 0
#define SM_WM_OFF (2 * AS_BUF * 2)            // bytes: 20480
#define SM_WV_OFF (SM_WM_OFF + 2 * WS_BUF * 2) // 20480 + 17408 = 37888
#define SM_TOTAL  (SM_WV_OFF + 2 * WS_BUF * 2) // 55296
#define NKIT (IN_F / GKC)   // 8

__global__ __launch_bounds__(256, 1)
void gemm_tc_kernel(const float* __restrict__ feat,
                    const float* __restrict__ Wm,
                    const float* __restrict__ Wv,
                    int n_nodes) {
    extern __shared__ __align__(16) char smem[];
    __half* As  = reinterpret_cast<__half*>(smem + SM_AS_OFF);
    __half* Wms = reinterpret_cast<__half*>(smem + SM_WM_OFF);
    __half* Wvs = reinterpret_cast<__half*>(smem + SM_WV_OFF);

    const int tid  = threadIdx.x;
    const int w    = tid >> 5;
    const int lane = tid & 31;
    const int node0 = blockIdx.x * GBM;

    // per-thread load slots (precompute indices)
    int a_row[4], a_kq[4], w_k[4], w_c4[4];
#pragma unroll
    for (int it = 0; it < 4; it++) {
        int idx = tid + 256 * it;
        a_row[it] = idx >> 3;
        a_kq[it]  = idx & 7;
        w_k[it]   = idx >> 5;
        w_c4[it]  = idx & 31;
    }

    wmma::fragment<wmma::accumulator, 16, 16, 16, float> accm[8], accv[8];
#pragma unroll
    for (int c = 0; c < 8; c++) {
        wmma::fill_fragment(accm[c], 0.0f);
        wmma::fill_fragment(accv[c], 0.0f);
    }

    float4 a_pf[4], wm_pf[4], wv_pf[4];

    // --- prefetch k0 = 0 ---
#pragma unroll
    for (int it = 0; it < 4; it++) {
        int node = node0 + a_row[it];
        a_pf[it] = make_float4(0.f, 0.f, 0.f, 0.f);
        if (node < n_nodes)
            a_pf[it] = *reinterpret_cast<const float4*>(&feat[(size_t)node * IN_F + a_kq[it] * 4]);
        wm_pf[it] = *reinterpret_cast<const float4*>(&Wm[(size_t)w_k[it] * OUT_F + w_c4[it] * 4]);
        wv_pf[it] = *reinterpret_cast<const float4*>(&Wv[(size_t)w_k[it] * OUT_F + w_c4[it] * 4]);
    }
    // store buf 0
#pragma unroll
    for (int it = 0; it < 4; it++) {
        *reinterpret_cast<__half2*>(&As[a_row[it] * AS_LD + a_kq[it] * 4])      = __floats2half2_rn(a_pf[it].x, a_pf[it].y);
        *reinterpret_cast<__half2*>(&As[a_row[it] * AS_LD + a_kq[it] * 4 + 2])  = __floats2half2_rn(a_pf[it].z, a_pf[it].w);
        *reinterpret_cast<__half2*>(&Wms[w_k[it] * WS_LD + w_c4[it] * 4])       = __floats2half2_rn(wm_pf[it].x, wm_pf[it].y);
        *reinterpret_cast<__half2*>(&Wms[w_k[it] * WS_LD + w_c4[it] * 4 + 2])   = __floats2half2_rn(wm_pf[it].z, wm_pf[it].w);
        *reinterpret_cast<__half2*>(&Wvs[w_k[it] * WS_LD + w_c4[it] * 4])       = __floats2half2_rn(wv_pf[it].x, wv_pf[it].y);
        *reinterpret_cast<__half2*>(&Wvs[w_k[it] * WS_LD + w_c4[it] * 4 + 2])   = __floats2half2_rn(wv_pf[it].z, wv_pf[it].w);
    }
    __syncthreads();

    for (int kit = 0; kit < NKIT; kit++) {
        const int buf = kit & 1;
        const int nbuf = 1 - buf;
        const int k0n = (kit + 1) * GKC;

        // prefetch next tile into registers (LDGs fly during MMAs)
        if (kit + 1 < NKIT) {
#pragma unroll
            for (int it = 0; it < 4; it++) {
                int node = node0 + a_row[it];
                a_pf[it] = make_float4(0.f, 0.f, 0.f, 0.f);
                if (node < n_nodes)
                    a_pf[it] = *reinterpret_cast<const float4*>(&feat[(size_t)node * IN_F + k0n + a_kq[it] * 4]);
                wm_pf[it] = *reinterpret_cast<const float4*>(&Wm[(size_t)(k0n + w_k[it]) * OUT_F + w_c4[it] * 4]);
                wv_pf[it] = *reinterpret_cast<const float4*>(&Wv[(size_t)(k0n + w_k[it]) * OUT_F + w_c4[it] * 4]);
            }
        }

        // MMAs on current buffer
        const __half* Ab  = As  + buf * AS_BUF;
        const __half* Wmb = Wms + buf * WS_BUF;
        const __half* Wvb = Wvs + buf * WS_BUF;
#pragma unroll
        for (int ks = 0; ks < GKC; ks += 16) {
            wmma::fragment<wmma::matrix_a, 16, 16, 16, __half, wmma::row_major> a;
            wmma::load_matrix_sync(a, &Ab[(w * 16) * AS_LD + ks], AS_LD);
#pragma unroll
            for (int c = 0; c < 8; c++) {
                wmma::fragment<wmma::matrix_b, 16, 16, 16, __half, wmma::row_major> b;
                wmma::load_matrix_sync(b, &Wmb[ks * WS_LD + c * 16], WS_LD);
                wmma::mma_sync(accm[c], a, b, accm[c]);
                wmma::load_matrix_sync(b, &Wvb[ks * WS_LD + c * 16], WS_LD);
                wmma::mma_sync(accv[c], a, b, accv[c]);
            }
        }

        // store prefetched tile into the other buffer
        if (kit + 1 < NKIT) {
            __half* Aw  = As  + nbuf * AS_BUF;
            __half* Wmw = Wms + nbuf * WS_BUF;
            __half* Wvw = Wvs + nbuf * WS_BUF;
#pragma unroll
            for (int it = 0; it < 4; it++) {
                *reinterpret_cast<__half2*>(&Aw[a_row[it] * AS_LD + a_kq[it] * 4])     = __floats2half2_rn(a_pf[it].x, a_pf[it].y);
                *reinterpret_cast<__half2*>(&Aw[a_row[it] * AS_LD + a_kq[it] * 4 + 2]) = __floats2half2_rn(a_pf[it].z, a_pf[it].w);
                *reinterpret_cast<__half2*>(&Wmw[w_k[it] * WS_LD + w_c4[it] * 4])      = __floats2half2_rn(wm_pf[it].x, wm_pf[it].y);
                *reinterpret_cast<__half2*>(&Wmw[w_k[it] * WS_LD + w_c4[it] * 4 + 2])  = __floats2half2_rn(wm_pf[it].z, wm_pf[it].w);
                *reinterpret_cast<__half2*>(&Wvw[w_k[it] * WS_LD + w_c4[it] * 4])      = __floats2half2_rn(wv_pf[it].x, wv_pf[it].y);
                *reinterpret_cast<__half2*>(&Wvw[w_k[it] * WS_LD + w_c4[it] * 4 + 2])  = __floats2half2_rn(wv_pf[it].z, wv_pf[it].w);
            }
            __syncthreads();
        }
    }

    // --- epilogue (stage aliases W smem region after barrier) ---
    __syncthreads();
    float* stage = reinterpret_cast<float*>(smem + SM_WM_OFF) + w * 256;

#pragma unroll
    for (int c = 0; c < 8; c++) {
#pragma unroll
        for (int i = 0; i < accm[c].num_elements; i++) {
            float mean = fmaxf(accm[c].x[i], 0.0f);
            float var  = fmaxf(accv[c].x[i], 0.0f);
            float att  = __expf(-var);       // GAMMA = 1
            accm[c].x[i] = mean * att;
            accv[c].x[i] = var * att * att;
        }
        wmma::store_matrix_sync(stage, accm[c], 16, wmma::mem_row_major);
        __syncwarp();
#pragma unroll
        for (int t = lane; t < 128; t += 32) {
            int r  = t >> 3;
            int c2 = t & 7;
            int node = node0 + w * 16 + r;
            if (node < n_nodes)
                *reinterpret_cast<__half2*>(&g_mh[(size_t)node * OUT_F + c * 16 + c2 * 2]) =
                    __floats2half2_rn(stage[r * 16 + c2 * 2], stage[r * 16 + c2 * 2 + 1]);
        }
        __syncwarp();
        wmma::store_matrix_sync(stage, accv[c], 16, wmma::mem_row_major);
        __syncwarp();
#pragma unroll
        for (int t = lane; t < 128; t += 32) {
            int r  = t >> 3;
            int c2 = t & 7;
            int node = node0 + w * 16 + r;
            if (node < n_nodes)
                *reinterpret_cast<__half2*>(&g_vh[(size_t)node * OUT_F + c * 16 + c2 * 2]) =
                    __floats2half2_rn(stage[r * 16 + c2 * 2], stage[r * 16 + c2 * 2 + 1]);
        }
        __syncwarp();
    }
}

// ---------------------------------------------------------------------
// Gather reduction: one block per dst node, 128 threads.
__global__ __launch_bounds__(128)
void gather_kernel(float* __restrict__ out_mean,
                   float* __restrict__ out_var) {
    const int d = blockIdx.x;
    const int tid = threadIdx.x;
    const bool is_var = tid >= 64;
    const int c = tid & 63;

    const int start = g_rp[d];
    const int end   = g_rp[d + 1];

    __shared__ int   sh_src[128];
    __shared__ float sh_w[128];

    const __half2* base = is_var ? reinterpret_cast<const __half2*>(g_vh)
                                 : reinterpret_cast<const __half2*>(g_mh);
    float2 acc = make_float2(0.0f, 0.0f);

    for (int e0 = start; e0 < end; e0 += 128) {
        int cnt = min(128, end - e0);
        if (tid < cnt) {
            int s = g_csrc[e0 + tid];
            sh_src[tid] = s;
            sh_w[tid] = g_norm1[s];
        }
        __syncthreads();
        int i = 0;
        for (; i + 4 <= cnt; i += 4) {
            int s0 = sh_src[i],     s1 = sh_src[i + 1];
            int s2 = sh_src[i + 2], s3 = sh_src[i + 3];
            float w0 = sh_w[i],     w1 = sh_w[i + 1];
            float w2 = sh_w[i + 2], w3 = sh_w[i + 3];
            float2 f0 = __half22float2(base[(size_t)s0 * (OUT_F / 2) + c]);
            float2 f1 = __half22float2(base[(size_t)s1 * (OUT_F / 2) + c]);
            float2 f2 = __half22float2(base[(size_t)s2 * (OUT_F / 2) + c]);
            float2 f3 = __half22float2(base[(size_t)s3 * (OUT_F / 2) + c]);
            if (is_var) { w0 *= w0; w1 *= w1; w2 *= w2; w3 *= w3; }
            acc.x = fmaf(w0, f0.x, acc.x); acc.y = fmaf(w0, f0.y, acc.y);
            acc.x = fmaf(w1, f1.x, acc.x); acc.y = fmaf(w1, f1.y, acc.y);
            acc.x = fmaf(w2, f2.x, acc.x); acc.y = fmaf(w2, f2.y, acc.y);
            acc.x = fmaf(w3, f3.x, acc.x); acc.y = fmaf(w3, f3.y, acc.y);
        }
        for (; i < cnt; i++) {
            int s = sh_src[i];
            float w = sh_w[i];
            if (is_var) w *= w;
            float2 f = __half22float2(base[(size_t)s * (OUT_F / 2) + c]);
            acc.x = fmaf(w, f.x, acc.x);
            acc.y = fmaf(w, f.y, acc.y);
        }
        __syncthreads();
    }

    float n1 = g_norm1[d];
    float scale = is_var ? n1 * n1 : n1;
    float* outp = is_var ? out_var : out_mean;
    float2 res = make_float2(acc.x * scale, acc.y * scale);
    *reinterpret_cast<float2*>(&outp[(size_t)d * OUT_F + c * 2]) = res;
}

// ---------------------------------------------------------------------
extern "C" void kernel_launch(void* const* d_in, const int* in_sizes, int n_in,
                              void* d_out, int out_size) {
    const float* feat     = (const float*)d_in[0];
    const int*   edge_src = (const int*)  d_in[1];
    const int*   edge_dst = (const int*)  d_in[2];
    const float* Wm       = (const float*)d_in[3];
    const float* Wv       = (const float*)d_in[4];

    const int n_nodes = in_sizes[0] / IN_F;
    const int n_edges = in_sizes[1];

    float* out_mean = (float*)d_out;
    float* out_var  = out_mean + (size_t)n_nodes * OUT_F;

    // one-time host-side resources (no device memory involved)
    static cudaStream_t s2 = nullptr;
    static cudaEvent_t evFork = nullptr, evJoin = nullptr;
    static void* cnt_addr = nullptr;
    if (!s2) {
        cudaStreamCreateWithFlags(&s2, cudaStreamNonBlocking);
        cudaEventCreateWithFlags(&evFork, cudaEventDisableTiming);
        cudaEventCreateWithFlags(&evJoin, cudaEventDisableTiming);
        cudaGetSymbolAddress(&cnt_addr, g_cnt);
        cudaFuncSetAttribute(gemm_tc_kernel,
                             cudaFuncAttributeMaxDynamicSharedMemorySize, SM_TOTAL);
    }

    // fork: CSR chain on s2, GEMM on main stream (independent since norm1
    // is consumed only in the gather phase)
    cudaEventRecord(evFork, 0);
    cudaStreamWaitEvent(s2, evFork, 0);

    // --- branch A (main stream): tensor-core GEMM ---
    gemm_tc_kernel<<<(n_nodes + GBM - 1) / GBM, 256, SM_TOTAL>>>(feat, Wm, Wv, n_nodes);

    // --- branch B (s2): CSR by dst + norms ---
    cudaMemsetAsync(cnt_addr, 0, (size_t)n_nodes * sizeof(int), s2);
    count_kernel<<<(n_edges + 255) / 256, 256, 0, s2>>>(edge_dst, n_edges);
    scan_fused_kernel<<<1, 1024, 0, s2>>>(n_nodes);
    fill_kernel<<<(n_edges + 255) / 256, 256, 0, s2>>>(edge_src, edge_dst, n_edges);

    // join
    cudaEventRecord(evJoin, s2);
    cudaStreamWaitEvent(0, evJoin, 0);

    // gather reduction (depends on both branches)
    gather_kernel<<<n_nodes, 128>>>(out_mean, out_var);
}